// round 16
// baseline (speedup 1.0000x reference)
#include <cuda_runtime.h>
#include <cuda_fp16.h>
#include <cstdint>

#define T_TOK 2048
#define HDIM  2048
#define IDIM  2048
#define NEXP  8
#define ROWS_PAD 5120          // 40 tiles * 128
#define MAX_TILES 40
#define WMAT ((size_t)2048 * 2048)

// KC=64 stages: A 0..18431 (128 rows * 144B pitch), B at 18432..34815
#define APITCH 144
#define BOFF   18432
#define STAGE  34816
#define NSTG   3
#define NCH    32              // 2048 / 64

// ---------------- device scratch ---------------------------------------------
__device__ __half   g_w1h[NEXP * WMAT];   // fp16 weights, same [E][K][N] layout
__device__ __half   g_w3h[NEXP * WMAT];
__device__ __half   g_w2h[NEXP * WMAT];
__device__ __half   g_xh[(size_t)T_TOK * HDIM];     // x fp16
__device__ __half   g_acth[(size_t)ROWS_PAD * IDIM]; // silu(g)*u fp16
__device__ int   g_row_token[ROWS_PAD];
__device__ float g_row_weight[ROWS_PAD];
__device__ int   g_tok_e[2 * T_TOK];
__device__ float g_tok_w[2 * T_TOK];
__device__ int   g_counts[NEXP];
__device__ int   g_cursor[NEXP];
__device__ int   g_seg_start[NEXP];
__device__ int   g_tile_e[MAX_TILES];
__device__ int   g_tile_row[MAX_TILES];

// ---------------- helpers ----------------------------------------------------
__device__ __forceinline__ uint32_t smem_u32(const void* p) {
    return (uint32_t)__cvta_generic_to_shared(p);
}
__device__ __forceinline__ void mma16816(float* c, const uint32_t* a, const uint32_t* b) {
    asm volatile(
        "mma.sync.aligned.m16n8k16.row.col.f32.f16.f16.f32 "
        "{%0,%1,%2,%3}, {%4,%5,%6,%7}, {%8,%9}, {%0,%1,%2,%3};"
        : "+f"(c[0]), "+f"(c[1]), "+f"(c[2]), "+f"(c[3])
        : "r"(a[0]), "r"(a[1]), "r"(a[2]), "r"(a[3]), "r"(b[0]), "r"(b[1]));
}
__device__ __forceinline__ void ldsm4(uint32_t* r, uint32_t a) {
    asm volatile("ldmatrix.sync.aligned.m8n8.x4.shared.b16 {%0,%1,%2,%3}, [%4];"
        : "=r"(r[0]), "=r"(r[1]), "=r"(r[2]), "=r"(r[3]) : "r"(a));
}
__device__ __forceinline__ void ldsm4t(uint32_t* r, uint32_t a) {
    asm volatile("ldmatrix.sync.aligned.m8n8.x4.trans.shared.b16 {%0,%1,%2,%3}, [%4];"
        : "=r"(r[0]), "=r"(r[1]), "=r"(r[2]), "=r"(r[3]) : "r"(a));
}
// cp.async 16B; n = src bytes (0 -> zero-fill)
__device__ __forceinline__ void cpa16(uint32_t d, const void* s, uint32_t n) {
    asm volatile("cp.async.cg.shared.global [%0], [%1], 16, %2;"
                 :: "r"(d), "l"(s), "r"(n) : "memory");
}
__device__ __forceinline__ void cpa16(uint32_t d, const void* s) {
    asm volatile("cp.async.cg.shared.global [%0], [%1], 16;"
                 :: "r"(d), "l"(s) : "memory");
}
#define CP_COMMIT() asm volatile("cp.async.commit_group;" ::: "memory")
__device__ __forceinline__ uint32_t cvt2(float a, float b) {
    __half2 h = __floats2half2_rn(a, b);
    return *(uint32_t*)&h;
}

// ---------------- reset ------------------------------------------------------
__global__ void reset_kernel(float* __restrict__ out) {
    int idx = blockIdx.x * 256 + threadIdx.x;
    if (idx < T_TOK * HDIM) out[idx] = 0.0f;
    if (idx < ROWS_PAD) g_row_token[idx] = -1;
    if (idx < NEXP) { g_counts[idx] = 0; g_cursor[idx] = 0; }
}

// ---------------- router -----------------------------------------------------
__global__ __launch_bounds__(256) void router_kernel(const float* __restrict__ x,
                                                     const float* __restrict__ gw) {
    int t = blockIdx.x;
    const float* xr = x + (size_t)t * HDIM;
    float acc[NEXP];
#pragma unroll
    for (int e = 0; e < NEXP; e++) acc[e] = 0.0f;
    for (int h = threadIdx.x; h < HDIM; h += 256) {
        float xv = xr[h];
#pragma unroll
        for (int e = 0; e < NEXP; e++) acc[e] = fmaf(xv, gw[e * HDIM + h], acc[e]);
    }
#pragma unroll
    for (int off = 16; off > 0; off >>= 1)
#pragma unroll
        for (int e = 0; e < NEXP; e++)
            acc[e] += __shfl_down_sync(0xffffffffu, acc[e], off);

    __shared__ float red[8][NEXP];
    int wid = threadIdx.x >> 5, lane = threadIdx.x & 31;
    if (lane == 0)
#pragma unroll
        for (int e = 0; e < NEXP; e++) red[wid][e] = acc[e];
    __syncthreads();

    if (threadIdx.x == 0) {
        float l[NEXP];
#pragma unroll
        for (int e = 0; e < NEXP; e++) {
            float s = 0.0f;
#pragma unroll
            for (int w = 0; w < 8; w++) s += red[w][e];
            l[e] = s;
        }
        int i0 = 0;
#pragma unroll
        for (int e = 1; e < NEXP; e++) if (l[e] > l[i0]) i0 = e;
        int i1 = -1;
#pragma unroll
        for (int e = 0; e < NEXP; e++)
            if (e != i0 && (i1 < 0 || l[e] > l[i1])) i1 = e;
        float w0 = 1.0f / (1.0f + expf(l[i1] - l[i0]));
        float w1 = 1.0f - w0;
        g_tok_e[2 * t] = i0;     g_tok_e[2 * t + 1] = i1;
        g_tok_w[2 * t] = w0;     g_tok_w[2 * t + 1] = w1;
        atomicAdd(&g_counts[i0], 1);
        atomicAdd(&g_counts[i1], 1);
    }
}

// ---------------- plan + scatter ---------------------------------------------
__global__ void plan_kernel() {
    if (threadIdx.x != 0) return;
    int off = 0, tile = 0;
    for (int e = 0; e < NEXP; e++) {
        g_seg_start[e] = off;
        int n = g_counts[e];
        int nt = (n + 127) >> 7;
        for (int j = 0; j < nt; j++) { g_tile_e[tile] = e; g_tile_row[tile] = off + (j << 7); tile++; }
        off += nt << 7;
    }
    for (; tile < MAX_TILES; tile++) g_tile_e[tile] = -1;
}

__global__ void scatter_kernel() {
    int t = blockIdx.x * 256 + threadIdx.x;
    if (t >= T_TOK) return;
#pragma unroll
    for (int k = 0; k < 2; k++) {
        int e = g_tok_e[2 * t + k];
        int r = atomicAdd(&g_cursor[e], 1);
        int row = g_seg_start[e] + r;
        g_row_token[row] = t;
        g_row_weight[row] = g_tok_w[2 * t + k];
    }
}

// ---------------- prep: weights + x fp32 -> fp16 -----------------------------
__global__ __launch_bounds__(256) void prep_w_kernel(const float* __restrict__ w1,
                                                     const float* __restrict__ w3,
                                                     const float* __restrict__ w2) {
    int mat = blockIdx.y;
    const float* src = (mat == 0 ? w1 : (mat == 1 ? w3 : w2));
    __half* dst = (mat == 0 ? g_w1h : (mat == 1 ? g_w3h : g_w2h));
    size_t i = ((size_t)blockIdx.x * 256 + threadIdx.x);
    float4 v = *(const float4*)(src + 4 * i);
    uint2 o;
    o.x = cvt2(v.x, v.y);
    o.y = cvt2(v.z, v.w);
    *(uint2*)(dst + 4 * i) = o;
}

__global__ __launch_bounds__(256) void prep_x_kernel(const float* __restrict__ x) {
    size_t i = ((size_t)blockIdx.x * 256 + threadIdx.x);
    float4 v = *(const float4*)(x + 4 * i);
    uint2 hi;
    hi.x = cvt2(v.x, v.y);
    hi.y = cvt2(v.z, v.w);
    *(uint2*)(g_xh + 4 * i) = hi;
}

// ---------------- GEMM1: HMMA fp16, fused gate+up + SiLU, KC=64 --------------
// CTA: M=128, N=64 (per mat), KC=64. 8 warps = 4(M) x 2(N), warp 32x32, dual acc.
__global__ __launch_bounds__(256, 2) void gemm1_kernel() {
    int e = g_tile_e[blockIdx.y];
    if (e < 0) return;
    int row_start = g_tile_row[blockIdx.y];
    int n0 = blockIdx.x * 64;
    extern __shared__ __align__(1024) char smem[];
    uint32_t SB = smem_u32(smem);

    const int tid = threadIdx.x;
    const int lane = tid & 31, wid = tid >> 5;
    const int wm = (wid & 3) * 32, wn = (wid >> 2) * 32;

    // staging maps (KC=64)
    const int bmat = tid >> 7;                  // 0:w1  1:w3
    const int bk = (tid & 127) >> 2;            // 0..31 (rows bk and bk+32)
    const int bn = (tid & 3) * 16;              // half col offset
    const __half* bsrc = (bmat ? g_w3h : g_w1h) + (size_t)e * WMAT + (size_t)bk * IDIM + n0 + bn;
    const int ar = tid >> 1;                    // 0..127
    const int akh = (tid & 1) * 32;             // K halfs
    int tok0 = g_row_token[row_start + ar];
    const uint32_t asz = (tok0 >= 0) ? 16u : 0u;
    const __half* axh = (tok0 >= 0) ? g_xh + (size_t)tok0 * HDIM + akh : g_xh;

    const uint32_t a_sts = (uint32_t)(ar * APITCH + akh * 2);
    const uint32_t bswz = (uint32_t)((bk & 7) * 16);
    const uint32_t b_base = (uint32_t)(BOFF + bmat * 8192 + bk * 128);
    const uint32_t b_sts0 = b_base + (((uint32_t)(bn * 2)) ^ bswz);
    const uint32_t b_sts1 = b_base + (((uint32_t)(bn * 2 + 16)) ^ bswz);

    float accG[2][4][4], accU[2][4][4];
#pragma unroll
    for (int i = 0; i < 2; i++)
#pragma unroll
        for (int j = 0; j < 4; j++)
#pragma unroll
            for (int q = 0; q < 4; q++) { accG[i][j][q] = 0.0f; accU[i][j][q] = 0.0f; }

#define G1_ISSUE(ch, slot) do {                                                   \
        uint32_t stb = SB + (uint32_t)(slot) * STAGE;                             \
        int k0 = (ch) * 64;                                                       \
        cpa16(stb + a_sts,      axh + k0,      asz);                              \
        cpa16(stb + a_sts + 16, axh + k0 + 8,  asz);                              \
        cpa16(stb + a_sts + 32, axh + k0 + 16, asz);                              \
        cpa16(stb + a_sts + 48, axh + k0 + 24, asz);                              \
        const __half* bp = bsrc + (size_t)k0 * IDIM;                              \
        cpa16(stb + b_sts0,        bp);                                           \
        cpa16(stb + b_sts1,        bp + 8);                                       \
        cpa16(stb + b_sts0 + 4096, bp + (size_t)32 * IDIM);                       \
        cpa16(stb + b_sts1 + 4096, bp + (size_t)32 * IDIM + 8);                   \
        CP_COMMIT();                                                              \
    } while (0)

    G1_ISSUE(0, 0);
    G1_ISSUE(1, 1);

    for (int c = 0; c < NCH; c++) {
        if (c < NCH - 1) asm volatile("cp.async.wait_group 1;" ::: "memory");
        else             asm volatile("cp.async.wait_group 0;" ::: "memory");
        __syncthreads();
        if (c + 2 < NCH) G1_ISSUE(c + 2, (c + 2) % NSTG);

        uint32_t stb = SB + (uint32_t)(c % NSTG) * STAGE;
#pragma unroll
        for (int s = 0; s < 4; s++) {
            uint32_t aH[2][4];
#pragma unroll
            for (int i = 0; i < 2; i++) {
                uint32_t ab = stb + (uint32_t)((wm + i * 16 + (lane & 15)) * APITCH +
                                               ((lane >> 4) * 16) + s * 32);
                ldsm4(aH[i], ab);
            }
            int krow = s * 16 + (lane & 15);
            uint32_t ksw = (uint32_t)((krow & 7) * 16);
            uint32_t rowb = (uint32_t)(krow * 128);
            uint32_t bf[2][4][2];
#pragma unroll
            for (int m = 0; m < 2; m++)
#pragma unroll
                for (int j2 = 0; j2 < 2; j2++) {
                    uint32_t chunk = (((uint32_t)((wn + j2 * 16) * 2 + (lane >> 4) * 16)) ^ ksw);
                    uint32_t r[4];
                    ldsm4t(r, stb + BOFF + (uint32_t)m * 8192 + rowb + chunk);
                    bf[m][j2 * 2][0] = r[0]; bf[m][j2 * 2][1] = r[1];
                    bf[m][j2 * 2 + 1][0] = r[2]; bf[m][j2 * 2 + 1][1] = r[3];
                }
#pragma unroll
            for (int i = 0; i < 2; i++)
#pragma unroll
                for (int j = 0; j < 4; j++) {
                    mma16816(accG[i][j], aH[i], bf[0][j]);
                    mma16816(accU[i][j], aH[i], bf[1][j]);
                }
        }
    }

    // epilogue: silu(G)*U -> g_acth (fp16)
    int r0 = lane >> 2, cc = 2 * (lane & 3);
#pragma unroll
    for (int i = 0; i < 2; i++)
#pragma unroll
        for (int j = 0; j < 4; j++) {
            int col = n0 + wn + j * 8 + cc;
#pragma unroll
            for (int h = 0; h < 2; h++) {
                int row = row_start + wm + i * 16 + r0 + h * 8;
                float g0 = accG[i][j][2 * h],     u0 = accU[i][j][2 * h];
                float g1 = accG[i][j][2 * h + 1], u1 = accU[i][j][2 * h + 1];
                float a0 = (g0 / (1.0f + __expf(-g0))) * u0;
                float a1 = (g1 / (1.0f + __expf(-g1))) * u1;
                *(uint32_t*)&g_acth[(size_t)row * IDIM + col] = cvt2(a0, a1);
            }
        }
#undef G1_ISSUE
}

// ---------------- GEMM2: HMMA fp16, down proj + weighted scatter, KC=64 ------
// CTA: M=128, N=128, KC=64. 8 warps = 2(M) x 4(N), warp 64x32. 2 CTAs/SM.
__global__ __launch_bounds__(256, 2) void gemm2_kernel(float* __restrict__ out) {
    int e = g_tile_e[blockIdx.y];
    if (e < 0) return;
    int row_start = g_tile_row[blockIdx.y];
    int n0 = blockIdx.x * 128;
    extern __shared__ __align__(1024) char smem[];
    uint32_t SB = smem_u32(smem);

    const int tid = threadIdx.x;
    const int lane = tid & 31, wid = tid >> 5;
    const int wm = (wid & 1) * 64, wn = (wid >> 1) * 32;

    const int ar = tid >> 1;
    const int akh = (tid & 1) * 32;             // halfs
    const __half* asrc = g_acth + (size_t)(row_start + ar) * IDIM + akh;
    const int bk = tid >> 3;                    // 0..31 (rows bk and bk+32)
    const int bn = (tid & 7) * 16;              // halfs
    const __half* bsrc = g_w2h + (size_t)e * WMAT + (size_t)bk * HDIM + n0 + bn;

    const uint32_t a_sts = (uint32_t)(ar * APITCH + akh * 2);
    const uint32_t bswz = (uint32_t)((bk & 7) * 16);
    const uint32_t b_base = (uint32_t)(BOFF + bk * 256);
    const uint32_t b_sts0 = b_base + (((uint32_t)(bn * 2)) ^ bswz);
    const uint32_t b_sts1 = b_base + (((uint32_t)(bn * 2 + 16)) ^ bswz);

    float acc[4][4][4];
#pragma unroll
    for (int i = 0; i < 4; i++)
#pragma unroll
        for (int j = 0; j < 4; j++)
#pragma unroll
            for (int q = 0; q < 4; q++) acc[i][j][q] = 0.0f;

#define G2_ISSUE(ch, slot) do {                                                   \
        uint32_t stb = SB + (uint32_t)(slot) * STAGE;                             \
        int k0 = (ch) * 64;                                                       \
        cpa16(stb + a_sts,      asrc + k0);                                       \
        cpa16(stb + a_sts + 16, asrc + k0 + 8);                                   \
        cpa16(stb + a_sts + 32, asrc + k0 + 16);                                  \
        cpa16(stb + a_sts + 48, asrc + k0 + 24);                                  \
        const __half* bp = bsrc + (size_t)k0 * HDIM;                              \
        cpa16(stb + b_sts0,        bp);                                           \
        cpa16(stb + b_sts1,        bp + 8);                                       \
        cpa16(stb + b_sts0 + 8192, bp + (size_t)32 * HDIM);                       \
        cpa16(stb + b_sts1 + 8192, bp + (size_t)32 * HDIM + 8);                   \
        CP_COMMIT();                                                              \
    } while (0)

    G2_ISSUE(0, 0);
    G2_ISSUE(1, 1);

    for (int c = 0; c < NCH; c++) {
        if (c < NCH - 1) asm volatile("cp.async.wait_group 1;" ::: "memory");
        else             asm volatile("cp.async.wait_group 0;" ::: "memory");
        __syncthreads();
        if (c + 2 < NCH) G2_ISSUE(c + 2, (c + 2) % NSTG);

        uint32_t stb = SB + (uint32_t)(c % NSTG) * STAGE;
#pragma unroll
        for (int s = 0; s < 4; s++) {
            uint32_t aH[4][4];
#pragma unroll
            for (int i = 0; i < 4; i++) {
                uint32_t ab = stb + (uint32_t)((wm + i * 16 + (lane & 15)) * APITCH +
                                               ((lane >> 4) * 16) + s * 32);
                ldsm4(aH[i], ab);
            }
            int krow = s * 16 + (lane & 15);
            uint32_t ksw = (uint32_t)((krow & 7) * 16);
            uint32_t rowb = (uint32_t)(krow * 256);
            uint32_t bf[4][2];
#pragma unroll
            for (int j2 = 0; j2 < 2; j2++) {
                uint32_t chunk = (((uint32_t)((wn + j2 * 16) * 2 + (lane >> 4) * 16)) ^ ksw);
                uint32_t r[4];
                ldsm4t(r, stb + BOFF + rowb + chunk);
                bf[j2 * 2][0] = r[0]; bf[j2 * 2][1] = r[1];
                bf[j2 * 2 + 1][0] = r[2]; bf[j2 * 2 + 1][1] = r[3];
            }
#pragma unroll
            for (int i = 0; i < 4; i++)
#pragma unroll
                for (int j = 0; j < 4; j++)
                    mma16816(acc[i][j], aH[i], bf[j]);
        }
    }

    // epilogue: weighted atomic scatter-add (2 adds/elem total -> deterministic)
    int r0 = lane >> 2, cc = 2 * (lane & 3);
#pragma unroll
    for (int i = 0; i < 4; i++)
#pragma unroll
        for (int h = 0; h < 2; h++) {
            int row = row_start + wm + i * 16 + r0 + h * 8;
            int tok = g_row_token[row];
            if (tok < 0) continue;
            float w = g_row_weight[row];
            float* ob = out + (size_t)tok * HDIM + n0;
#pragma unroll
            for (int j = 0; j < 4; j++) {
                int col = wn + j * 8 + cc;
                atomicAdd(ob + col,     w * acc[i][j][2 * h]);
                atomicAdd(ob + col + 1, w * acc[i][j][2 * h + 1]);
            }
        }
#undef G2_ISSUE
}

// ---------------- launch -----------------------------------------------------
extern "C" void kernel_launch(void* const* d_in, const int* in_sizes, int n_in,
                              void* d_out, int out_size) {
    const float* x  = (const float*)d_in[0];
    const float* gw = (const float*)d_in[1];
    const float* w1 = (const float*)d_in[2];
    const float* w3 = (const float*)d_in[3];
    const float* w2 = (const float*)d_in[4];
    float* out = (float*)d_out;

    cudaFuncSetAttribute(gemm1_kernel, cudaFuncAttributeMaxDynamicSharedMemorySize, NSTG * STAGE);
    cudaFuncSetAttribute(gemm2_kernel, cudaFuncAttributeMaxDynamicSharedMemorySize, NSTG * STAGE);

    reset_kernel<<<(T_TOK * HDIM + 255) / 256, 256>>>(out);
    router_kernel<<<T_TOK, 256>>>(x, gw);
    plan_kernel<<<1, 32>>>();
    scatter_kernel<<<(T_TOK + 255) / 256, 256>>>();
    prep_w_kernel<<<dim3(32768, 3), 256>>>(w1, w3, w2);
    prep_x_kernel<<<4096, 256>>>(x);

    gemm1_kernel<<<dim3(32, MAX_TILES), 256, NSTG * STAGE>>>();
    gemm2_kernel<<<dim3(16, MAX_TILES), 256, NSTG * STAGE>>>(out);
}